// round 16
// baseline (speedup 1.0000x reference)
#include <cuda_runtime.h>
#include <cstdint>

constexpr int N_IN   = 16384;
constexpr int T_OUT  = 8195;           // ((N+13)-8)/2+1
constexpr int OUTROW = 2 * T_OUT;      // 16390

constexpr int THREADS        = 256;
constexpr int WARPS          = THREADS / 32;                        // 8
constexpr int T_PER_WARP     = 128;                                 // 4 t per lane
constexpr int WARPS_PER_ROW  = (T_OUT + T_PER_WARP - 1) / T_PER_WARP;   // 65
constexpr int BLOCKS_PER_ROW = (WARPS_PER_ROW + WARPS - 1) / WARPS;     // 9

// time-reversed filters (compile-time immediates -> FFMA-imm)
__device__ constexpr float LO[8] = {  0.23037781330885523f,  0.7148465705525415f,
                                      0.6308807679295904f,  -0.02798376941698385f,
                                     -0.18703481171888114f,  0.030841381835986965f,
                                      0.032883011666982945f,-0.010597401784997278f };
__device__ constexpr float HI[8] = { -0.010597401784997278f,-0.032883011666982945f,
                                      0.030841381835986965f, 0.18703481171888114f,
                                     -0.02798376941698385f, -0.6308807679295904f,
                                      0.7148465705525415f,  -0.23037781330885523f };

// sig[i] -> x index with symmetric mirror (verified rel_err==0)
__device__ __forceinline__ int map_sig(int i) {
    int m = i - 6;
    m = (m < 0) ? (-1 - m) : m;
    m = (m >= N_IN) ? (2 * N_IN - 1 - m) : m;
    return m;
}

// scalar mirrored path for boundary t's
__device__ __forceinline__ void slow_t(const float* __restrict__ xr, int t,
                                       float& a, float& d) {
    a = 0.f; d = 0.f;
    #pragma unroll
    for (int j = 0; j < 8; j++) {
        const float s = __ldg(xr + map_sig(2 * t + j));
        a = fmaf(LO[j], s, a);
        d = fmaf(HI[j], s, d);
    }
}

// 256-bit global load (sm_100+), 32B-aligned, with L2 256B prefetch hint
__device__ __forceinline__ void ldg256(const float* __restrict__ p, float r[8]) {
    asm ("ld.global.nc.L2::256B.v8.f32 {%0,%1,%2,%3,%4,%5,%6,%7}, [%8];"
         : "=f"(r[0]), "=f"(r[1]), "=f"(r[2]), "=f"(r[3]),
           "=f"(r[4]), "=f"(r[5]), "=f"(r[6]), "=f"(r[7])
         : "l"(p));
}

__global__ __launch_bounds__(THREADS) void dwt_kernel(const float* __restrict__ x,
                                                      float* __restrict__ out)
{
    const int row  = blockIdx.y;
    const int wid  = threadIdx.x >> 5;
    const int lane = threadIdx.x & 31;
    const int wir  = blockIdx.x * WARPS + wid;           // warp index within row
    if (wir >= WARPS_PER_ROW) return;                    // uniform whole-warp exit

    const float* __restrict__ xr = x + (size_t)row * N_IN;

    const int t = wir * T_PER_WARP + 4 * lane;           // this lane's 4-t start
    const int b = 2 * t - 8;                             // own data base (mult of 8)

    // only warp 0 (b<0) and the tail warp can go OOB
    const bool edge = (wir == 0) | (wir == WARPS_PER_ROW - 1);

    // own 8 floats: ONE contiguous LDG.256 per lane (1KB contiguous per warp)
    float r[8];
    {
        int b0 = b;
        if (edge) b0 = min(max(b, 0), N_IN - 8);         // stays 32B-aligned
        ldg256(xr + b0, r);
    }

    // lane 31: direct load replacing out-of-warp shfl source (x[b+8..b+15])
    float p[8];
    if (lane == 31) {
        int b1 = b + 8;
        if (edge) b1 = min(max(b1, 0), N_IN - 8);
        ldg256(xr + b1, p);
    }

    // neighbor lane's 8 floats via shuffle crossbar
    float n[8];
    #pragma unroll
    for (int j = 0; j < 8; j++)
        n[j] = __shfl_down_sync(0xffffffffu, r[j], 1);
    if (lane == 31) {
        #pragma unroll
        for (int j = 0; j < 8; j++) n[j] = p[j];
    }

    // f[j] = sig[2t+j] = x[b+2+j], j = 0..13
    const float f[14] = { r[2], r[3], r[4], r[5], r[6], r[7],
                          n[0], n[1], n[2], n[3], n[4], n[5], n[6], n[7] };

    float ca0=0.f, ca1=0.f, ca2=0.f, ca3=0.f;
    float cd0=0.f, cd1=0.f, cd2=0.f, cd3=0.f;
    #pragma unroll
    for (int j = 0; j < 8; j++) {
        ca0 = fmaf(LO[j], f[j    ], ca0);  cd0 = fmaf(HI[j], f[j    ], cd0);
        ca1 = fmaf(LO[j], f[j + 2], ca1);  cd1 = fmaf(HI[j], f[j + 2], cd1);
        ca2 = fmaf(LO[j], f[j + 4], ca2);  cd2 = fmaf(HI[j], f[j + 4], cd2);
        ca3 = fmaf(LO[j], f[j + 6], ca3);  cd3 = fmaf(HI[j], f[j + 6], cd3);
    }

    // boundary overwrite (mirrored taps or clamped base): t in [0,3] U [8191,8194]
    if (t < 4 || t + 3 > 8190) {
        if ((t     < 4 || t     > 8190) && t     < T_OUT) slow_t(xr, t,     ca0, cd0);
        if ((t + 1 < 4 || t + 1 > 8190) && t + 1 < T_OUT) slow_t(xr, t + 1, ca1, cd1);
        if ((t + 2 < 4 || t + 2 > 8190) && t + 2 < T_OUT) slow_t(xr, t + 2, ca2, cd2);
        if ((t + 3 < 4 || t + 3 > 8190) && t + 3 < T_OUT) slow_t(xr, t + 3, ca3, cd3);
    }

    float* __restrict__ orow = out + (size_t)row * OUTROW;
    const bool full_warp = (wir * T_PER_WARP + T_PER_WARP) <= T_OUT;   // warp-uniform

    if (full_warp) {
        // ---- aligned, shuffle-shifted STG.128 stores ----
        float* __restrict__ gA = orow + t;            // elem index ≡ {0,2} mod 4
        float* __restrict__ gD = orow + T_OUT + t;    // elem index ≡ {3,1} mod 4

        if (((size_t)row & 1) == 0) {
            // cA aligned directly
            *reinterpret_cast<float4*>(gA) = make_float4(ca0, ca1, ca2, ca3);
            // cD: shift 1 -> {cd1,cd2,cd3,next.cd0} at gD+1
            const float nd0 = __shfl_down_sync(0xffffffffu, cd0, 1);
            if (lane < 31) {
                *reinterpret_cast<float4*>(gD + 1) = make_float4(cd1, cd2, cd3, nd0);
            } else {
                gD[1] = cd1; gD[2] = cd2; gD[3] = cd3;
            }
            if (lane == 0) gD[0] = cd0;
        } else {
            // cA: shift 2 -> {ca2,ca3,next.ca0,next.ca1} at gA+2
            const float na0 = __shfl_down_sync(0xffffffffu, ca0, 1);
            const float na1 = __shfl_down_sync(0xffffffffu, ca1, 1);
            if (lane < 31) {
                *reinterpret_cast<float4*>(gA + 2) = make_float4(ca2, ca3, na0, na1);
            } else {
                gA[2] = ca2; gA[3] = ca3;
            }
            if (lane == 0) { gA[0] = ca0; gA[1] = ca1; }
            // cD: shift 3 -> {cd3,next.cd0,next.cd1,next.cd2} at gD+3
            const float nd0 = __shfl_down_sync(0xffffffffu, cd0, 1);
            const float nd1 = __shfl_down_sync(0xffffffffu, cd1, 1);
            const float nd2 = __shfl_down_sync(0xffffffffu, cd2, 1);
            if (lane < 31) {
                *reinterpret_cast<float4*>(gD + 3) = make_float4(cd3, nd0, nd1, nd2);
            } else {
                gD[3] = cd3;
            }
            if (lane == 0) { gD[0] = cd0; gD[1] = cd1; gD[2] = cd2; }
        }
    } else {
        // tail warp: scalar bounded stores
        const float ca[4] = { ca0, ca1, ca2, ca3 };
        const float cd[4] = { cd0, cd1, cd2, cd3 };
        #pragma unroll
        for (int v = 0; v < 4; v++) {
            if (t + v < T_OUT) {
                orow[t + v]         = ca[v];
                orow[T_OUT + t + v] = cd[v];
            }
        }
    }
}

extern "C" void kernel_launch(void* const* d_in, const int* in_sizes, int n_in,
                              void* d_out, int out_size)
{
    const float* x = (const float*)d_in[0];
    float* out = (float*)d_out;
    const int rows = in_sizes[0] / N_IN;   // 4096
    dim3 grid(BLOCKS_PER_ROW, rows);
    dwt_kernel<<<grid, THREADS>>>(x, out);
}